// round 5
// baseline (speedup 1.0000x reference)
#include <cuda_runtime.h>

#define D_DIM 25000
#define B_DIM 64
#define K_DIM 16
#define H_DIM 128
#define E_DIM 256
#define Z_DIM 32

#define GRID2 625
#define CHUNKS (D_DIM / 8)          // 3125 chunks of 8 d's

// ---- scratch (device globals; no allocations allowed) ----
__device__ float g_buf[D_DIM * H_DIM];          // 12.8 MB: g[d][j]
__device__ float c_part[GRID2 * B_DIM * K_DIM]; // per-block partial pooled c
__device__ float c_buf[B_DIM * K_DIM];          // pooled c [64][16]
__device__ float hE_buf[B_DIM * E_DIM];         // encoder hidden [64][256]

#define FMA2(s, a, b) \
    asm("fma.rn.f32x2 %0, %1, %2, %0;" : "+l"(s) : "l"(a), "l"(b))
#define PACK2(dst, lo, hi) \
    asm("mov.b64 %0, {%1, %2};" : "=l"(dst) \
        : "r"(__float_as_uint(lo)), "r"(__float_as_uint(hi)))
#define UNPACK2(lo, hi, src) \
    do { unsigned int _ul, _uh; \
         asm("mov.b64 {%0, %1}, %2;" : "=r"(_ul), "=r"(_uh) : "l"(src)); \
         lo = __uint_as_float(_ul); hi = __uint_as_float(_uh); } while (0)

// ---------------------------------------------------------------------------
// Kernel 1: g[d][j] = b1[j] + feat_bias[d]*W1[17][j] + sum_i feat_emb[d][i]*W1[1+i][j]
// ---------------------------------------------------------------------------
__global__ void k_g(const float* __restrict__ fe, const float* __restrict__ fb,
                    const float* __restrict__ W1, const float* __restrict__ b1)
{
    int d = blockIdx.x;
    int j = threadIdx.x;                     // 128 threads
    float acc = b1[j] + fb[d] * W1[17 * H_DIM + j];
    const float* fr = fe + d * K_DIM;
#pragma unroll
    for (int i = 0; i < K_DIM; i++)
        acc = fmaf(fr[i], W1[(1 + i) * H_DIM + j], acc);
    g_buf[d * H_DIM + j] = acc;
}

// ---------------------------------------------------------------------------
// Kernel 2: main. Thread (p,q) handles batch pair (2p, 2p+1) at one d per chunk.
// Warp = 32 p's at same d -> all W2/g shared loads are broadcasts.
// Stage-2 runs packed f32x2 over the batch pair.
// ---------------------------------------------------------------------------
__global__ __launch_bounds__(256, 2)
void k_main(const float* __restrict__ x, const int* __restrict__ mask,
            const float* __restrict__ W1, const float* __restrict__ W2,
            const float* __restrict__ b2)
{
    __shared__ __align__(16) unsigned long long W2s[H_DIM * K_DIM]; // 16 KB, dup pairs
    __shared__ __align__(16) float w0s[H_DIM];
    __shared__ unsigned long long b2s[K_DIM];
    __shared__ __align__(16) float gs[8 * H_DIM];                   // 4 KB
    __shared__ __align__(16) float xs[8][B_DIM];                    // 2 KB
    __shared__ __align__(16) float ms[8][B_DIM];                    // 2 KB
    __shared__ float csh[B_DIM * K_DIM];                            // 4 KB

    const int t = threadIdx.x;

    // stage W2 duplicated into both f32x2 halves
    for (int i = t; i < H_DIM * K_DIM; i += 256) {
        float w = W2[i];
        unsigned long long dd; PACK2(dd, w, w);
        W2s[i] = dd;
    }
    if (t < H_DIM) w0s[t] = W1[t];           // W1 row 0 (the x weight)
    if (t < K_DIM) { float b = b2[t]; unsigned long long dd; PACK2(dd, b, b); b2s[t] = dd; }
    for (int i = t; i < B_DIM * K_DIM; i += 256) csh[i] = 0.f;
    __syncthreads();

    const int q = t >> 5;                    // 0..7  (which d in chunk)
    const int p = t & 31;                    // 0..31 (batch pair)

    float acc0[K_DIM], acc1[K_DIM];
#pragma unroll
    for (int k = 0; k < K_DIM; k++) { acc0[k] = 0.f; acc1[k] = 0.f; }

    for (int cc = blockIdx.x; cc < CHUNKS; cc += gridDim.x) {
        const int d0 = cc * 8;

        // cooperative loads for this chunk
        ((float4*)gs)[t] = ((const float4*)(g_buf + d0 * H_DIM))[t]; // 1024 floats
        for (int i = t; i < 512; i += 256) {
            int b = i >> 3, qq = i & 7;
            int gi = b * D_DIM + d0 + qq;
            xs[qq][b] = x[gi];
            ms[qq][b] = (float)mask[gi];
        }
        __syncthreads();

        const float2 xv = *(const float2*)&xs[q][2 * p];
        const float2 mv = *(const float2*)&ms[q][2 * p];

        unsigned long long s[K_DIM];
#pragma unroll
        for (int k = 0; k < K_DIM; k++) s[k] = b2s[k];

        const float* grow = gs + q * H_DIM;
#pragma unroll 2
        for (int j4 = 0; j4 < H_DIM; j4 += 4) {
            const float4 g4 = *(const float4*)(grow + j4);
            const float4 w4 = *(const float4*)(w0s + j4);
#pragma unroll
            for (int jj = 0; jj < 4; jj++) {
                const float gj = (&g4.x)[jj];
                const float wj = (&w4.x)[jj];
                const float h0 = fmaxf(fmaf(xv.x, wj, gj), 0.f);
                const float h1 = fmaxf(fmaf(xv.y, wj, gj), 0.f);
                unsigned long long hp; PACK2(hp, h0, h1);
                const ulonglong2* wr = (const ulonglong2*)&W2s[(j4 + jj) * K_DIM];
#pragma unroll
                for (int k2 = 0; k2 < 8; k2++) {
                    ulonglong2 ww = wr[k2];
                    FMA2(s[2 * k2],     hp, ww.x);
                    FMA2(s[2 * k2 + 1], hp, ww.y);
                }
            }
        }

        // epilogue: relu + masked accumulate (scalar; 16/2048 of the work)
#pragma unroll
        for (int k = 0; k < K_DIM; k++) {
            float lo, hi; UNPACK2(lo, hi, s[k]);
            acc0[k] = fmaf(mv.x, fmaxf(lo, 0.f), acc0[k]);
            acc1[k] = fmaf(mv.y, fmaxf(hi, 0.f), acc1[k]);
        }
        __syncthreads();
    }

    // block-local reduction over q via shared atomics, then coalesced partial store
    const int b0 = 2 * p, b1r = 2 * p + 1;
#pragma unroll
    for (int k = 0; k < K_DIM; k++) {
        atomicAdd(&csh[b0  * K_DIM + k], acc0[k]);
        atomicAdd(&csh[b1r * K_DIM + k], acc1[k]);
    }
    __syncthreads();
    for (int i = t; i < B_DIM * K_DIM; i += 256)
        c_part[blockIdx.x * (B_DIM * K_DIM) + i] = csh[i];
}

// ---------------------------------------------------------------------------
// Kernel 3: deterministic reduction of per-block partials
// ---------------------------------------------------------------------------
__global__ void k_reduce()
{
    int i = blockIdx.x * blockDim.x + threadIdx.x;  // 1024 threads total
    float s0 = 0.f, s1 = 0.f, s2 = 0.f, s3 = 0.f;
    int bk = 0;
    for (; bk + 4 <= GRID2; bk += 4) {
        s0 += c_part[(bk + 0) * 1024 + i];
        s1 += c_part[(bk + 1) * 1024 + i];
        s2 += c_part[(bk + 2) * 1024 + i];
        s3 += c_part[(bk + 3) * 1024 + i];
    }
    for (; bk < GRID2; bk++) s0 += c_part[bk * 1024 + i];
    c_buf[i] = (s0 + s1) + (s2 + s3);
}

// ---------------------------------------------------------------------------
// Kernel 4: encoder layer 1: hE = relu(c @ We1 + be1)   [64,16]@[16,256]
// ---------------------------------------------------------------------------
__global__ void k_encA(const float* __restrict__ We1, const float* __restrict__ be1)
{
    __shared__ float cb[K_DIM];
    int b = blockIdx.x, e = threadIdx.x;     // 256 threads
    if (e < K_DIM) cb[e] = c_buf[b * K_DIM + e];
    __syncthreads();
    float acc = be1[e];
#pragma unroll
    for (int k = 0; k < K_DIM; k++)
        acc = fmaf(cb[k], We1[k * E_DIM + e], acc);
    hE_buf[b * E_DIM + e] = fmaxf(acc, 0.f);
}

// ---------------------------------------------------------------------------
// Kernel 5: encoder layer 2 + split-layout output (mu then logvar)
// ---------------------------------------------------------------------------
__global__ void k_encB(const float* __restrict__ We2, const float* __restrict__ be2,
                       float* __restrict__ out)
{
    __shared__ float hr[E_DIM];
    int b = blockIdx.x, o = threadIdx.x;     // 64 threads
    for (int i = o; i < E_DIM; i += 64) hr[i] = hE_buf[b * E_DIM + i];
    __syncthreads();
    float acc = be2[o];
#pragma unroll 8
    for (int e = 0; e < E_DIM; e++)
        acc = fmaf(hr[e], We2[e * (2 * Z_DIM) + o], acc);
    if (o < Z_DIM)
        out[b * Z_DIM + o] = acc;                                   // mu
    else
        out[B_DIM * Z_DIM + b * Z_DIM + (o - Z_DIM)] = acc;         // logvar
}

// ---------------------------------------------------------------------------
extern "C" void kernel_launch(void* const* d_in, const int* in_sizes, int n_in,
                              void* d_out, int out_size)
{
    const float* x    = (const float*)d_in[0];
    const int*   mask = (const int*)  d_in[1];
    const float* fe   = (const float*)d_in[2];
    const float* fb   = (const float*)d_in[3];
    const float* W1   = (const float*)d_in[4];
    const float* b1   = (const float*)d_in[5];
    const float* W2   = (const float*)d_in[6];
    const float* b2   = (const float*)d_in[7];
    const float* We1  = (const float*)d_in[8];
    const float* be1  = (const float*)d_in[9];
    const float* We2  = (const float*)d_in[10];
    const float* be2  = (const float*)d_in[11];
    float* out = (float*)d_out;

    k_g     <<<D_DIM, H_DIM>>>(fe, fb, W1, b1);
    k_main  <<<GRID2, 256>>>(x, mask, W1, W2, b2);
    k_reduce<<<4, 256>>>();
    k_encA  <<<B_DIM, E_DIM>>>(We1, be1);
    k_encB  <<<B_DIM, 2 * Z_DIM>>>(We2, be2, out);
}

// round 6
// speedup vs baseline: 1.7385x; 1.7385x over previous
#include <cuda_runtime.h>

#define D_DIM 25000
#define B_DIM 64
#define K_DIM 16
#define H_DIM 128
#define E_DIM 256
#define Z_DIM 32

#define NBLK   592              // = 148 SMs x 4 CTAs -> exactly one wave
#define CHUNKS 3125             // 8 d's per chunk
#define CSTR   17               // padded c stride (bank-conflict relief)

typedef unsigned long long ull;

// ---- scratch (device globals; no allocations allowed) ----
__device__ float g_buf[D_DIM * H_DIM];          // 12.8 MB: g[d][j]
__device__ float c_part[NBLK * B_DIM * K_DIM];  // per-block partial pooled c
__device__ float c_buf[B_DIM * K_DIM];          // pooled c [64][16]

#define FMA2(s, a, b) \
    asm("fma.rn.f32x2 %0, %1, %2, %0;" : "+l"(s) : "l"(a), "l"(b))
#define PACK2(dst, lo, hi) \
    asm("mov.b64 %0, {%1, %2};" : "=l"(dst) \
        : "r"(__float_as_uint(lo)), "r"(__float_as_uint(hi)))
#define UNPACK2(lo, hi, src) \
    do { unsigned int _ul, _uh; \
         asm("mov.b64 {%0, %1}, %2;" : "=r"(_ul), "=r"(_uh) : "l"(src)); \
         lo = __uint_as_float(_ul); hi = __uint_as_float(_uh); } while (0)

// ---------------------------------------------------------------------------
// Kernel 1: g[d][j] = b1[j] + feat_bias[d]*W1[17][j] + sum_i feat_emb[d][i]*W1[1+i][j]
// ---------------------------------------------------------------------------
__global__ void k_g(const float* __restrict__ fe, const float* __restrict__ fb,
                    const float* __restrict__ W1, const float* __restrict__ b1)
{
    int d = blockIdx.x;
    int j = threadIdx.x;                     // 128 threads
    float acc = b1[j] + fb[d] * W1[17 * H_DIM + j];
    const float* fr = fe + d * K_DIM;
#pragma unroll
    for (int i = 0; i < K_DIM; i++)
        acc = fmaf(fr[i], W1[(1 + i) * H_DIM + j], acc);
    g_buf[d * H_DIM + j] = acc;
}

// ---------------------------------------------------------------------------
// Kernel 2: main. Block = 128 threads = 4 q x 32 p.
//   thread: d-pair (2q, 2q+1) within an 8-d chunk, batch pair (2p, 2p+1).
//   Each W2 row LDS feeds BOTH d's (32 FFMA2 per 8 LDS.128).
//   Per-block c accumulated via padded shared atomics; one partial store/block.
// ---------------------------------------------------------------------------
__global__ __launch_bounds__(128, 4)
void k_main(const float* __restrict__ x, const int* __restrict__ mask,
            const float* __restrict__ W1, const float* __restrict__ W2,
            const float* __restrict__ b2)
{
    __shared__ __align__(16) ull   W2s[H_DIM * K_DIM];   // 16 KB, dup pairs
    __shared__ __align__(16) float w0s[H_DIM];
    __shared__ ull                 b2s[K_DIM];
    __shared__ __align__(16) float gs[8 * H_DIM];        // 4 KB
    __shared__ __align__(16) float xs[8][B_DIM];         // 2 KB
    __shared__ __align__(16) float ms[8][B_DIM];         // 2 KB
    __shared__ float csh[B_DIM * CSTR];                  // padded 4.35 KB

    const int t = threadIdx.x;

    for (int i = t; i < H_DIM * K_DIM; i += 128) {
        float w = W2[i];
        ull dd; PACK2(dd, w, w);
        W2s[i] = dd;
    }
    if (t < H_DIM) w0s[t] = W1[t];           // W1 row 0 (the x weight)
    if (t < K_DIM) { float b = b2[t]; ull dd; PACK2(dd, b, b); b2s[t] = dd; }
    for (int i = t; i < B_DIM * CSTR; i += 128) csh[i] = 0.f;
    __syncthreads();

    const int q = t >> 5;                    // 0..3  (d-pair in chunk)
    const int p = t & 31;                    // 0..31 (batch pair)
    const int dA = 2 * q, dB = 2 * q + 1;

    // contiguous balanced chunk partition: 3125 = 165*6 + 427*5
    int cnt, base;
    if (blockIdx.x < 165) { cnt = 6; base = blockIdx.x * 6; }
    else                  { cnt = 5; base = 165 * 6 + (blockIdx.x - 165) * 5; }

    for (int ci = 0; ci < cnt; ci++) {
        const int d0 = (base + ci) * 8;

        // cooperative staging
        {
            const float4* src = (const float4*)(g_buf + d0 * H_DIM); // 256 float4
            ((float4*)gs)[t]       = src[t];
            ((float4*)gs)[t + 128] = src[t + 128];
            for (int i = t; i < 512; i += 128) {
                int b = i >> 3, qq = i & 7;
                int gi = b * D_DIM + d0 + qq;
                xs[qq][b] = x[gi];
                ms[qq][b] = (float)mask[gi];
            }
        }
        __syncthreads();

        const float2 xvA = *(const float2*)&xs[dA][2 * p];
        const float2 xvB = *(const float2*)&xs[dB][2 * p];

        ull sA[K_DIM], sB[K_DIM];
#pragma unroll
        for (int k = 0; k < K_DIM; k++) { sA[k] = b2s[k]; sB[k] = b2s[k]; }

        const float* gA = gs + dA * H_DIM;
        const float* gB = gs + dB * H_DIM;

#pragma unroll 2
        for (int j4 = 0; j4 < H_DIM; j4 += 4) {
            const float4 a4 = *(const float4*)(gA + j4);
            const float4 c4 = *(const float4*)(gB + j4);
            const float4 w4 = *(const float4*)(w0s + j4);
#pragma unroll
            for (int jj = 0; jj < 4; jj++) {
                const float wj  = (&w4.x)[jj];
                const float gAj = (&a4.x)[jj];
                const float gBj = (&c4.x)[jj];
                const float hA0 = fmaxf(fmaf(xvA.x, wj, gAj), 0.f);
                const float hA1 = fmaxf(fmaf(xvA.y, wj, gAj), 0.f);
                const float hB0 = fmaxf(fmaf(xvB.x, wj, gBj), 0.f);
                const float hB1 = fmaxf(fmaf(xvB.y, wj, gBj), 0.f);
                ull hpA; PACK2(hpA, hA0, hA1);
                ull hpB; PACK2(hpB, hB0, hB1);
                const ulonglong2* wr = (const ulonglong2*)&W2s[(j4 + jj) * K_DIM];
#pragma unroll
                for (int k2 = 0; k2 < 8; k2++) {
                    ulonglong2 ww = wr[k2];
                    FMA2(sA[2 * k2],     hpA, ww.x);
                    FMA2(sA[2 * k2 + 1], hpA, ww.y);
                    FMA2(sB[2 * k2],     hpB, ww.x);
                    FMA2(sB[2 * k2 + 1], hpB, ww.y);
                }
            }
        }

        // epilogue: relu + mask, combine d-pair, one shared atomic per (b,k)
        const float mA0 = ms[dA][2 * p], mA1 = ms[dA][2 * p + 1];
        const float mB0 = ms[dB][2 * p], mB1 = ms[dB][2 * p + 1];
        const int c0 = (2 * p) * CSTR, c1 = (2 * p + 1) * CSTR;
#pragma unroll
        for (int k = 0; k < K_DIM; k++) {
            float aLo, aHi, bLo, bHi;
            UNPACK2(aLo, aHi, sA[k]);
            UNPACK2(bLo, bHi, sB[k]);
            float v0 = fmaf(mA0, fmaxf(aLo, 0.f), mB0 * fmaxf(bLo, 0.f));
            float v1 = fmaf(mA1, fmaxf(aHi, 0.f), mB1 * fmaxf(bHi, 0.f));
            atomicAdd(&csh[c0 + k], v0);
            atomicAdd(&csh[c1 + k], v1);
        }
        __syncthreads();   // protect gs/xs/ms before next staging
    }

    // un-padded coalesced partial store
    for (int i = t; i < B_DIM * K_DIM; i += 128) {
        int b = i >> 4, k = i & 15;
        c_part[blockIdx.x * (B_DIM * K_DIM) + i] = csh[b * CSTR + k];
    }
}

// ---------------------------------------------------------------------------
// Kernel 3: reduce 592 partials -> c_buf.  grid 32 x 256; 8 lanes per output.
// ---------------------------------------------------------------------------
__global__ void k_reduce()
{
    const int t = threadIdx.x;
    const int o = blockIdx.x * 32 + (t >> 3);   // 0..1023
    const int s = t & 7;
    float a0 = 0.f, a1 = 0.f;
    for (int bk = s; bk < NBLK; bk += 16) {     // 592 = 16*37
        a0 += c_part[bk * 1024 + o];
        a1 += c_part[(bk + 8) * 1024 + o];
    }
    float v = a0 + a1;
    v += __shfl_xor_sync(0xffffffff, v, 4);
    v += __shfl_xor_sync(0xffffffff, v, 2);
    v += __shfl_xor_sync(0xffffffff, v, 1);
    if (s == 0) c_buf[o] = v;
}

// ---------------------------------------------------------------------------
// Kernel 4: fused encoder MLP + split (mu||logvar) output layout.
// ---------------------------------------------------------------------------
__global__ void k_enc(const float* __restrict__ We1, const float* __restrict__ be1,
                      const float* __restrict__ We2, const float* __restrict__ be2,
                      float* __restrict__ out)
{
    __shared__ float cb[K_DIM];
    __shared__ float hE[E_DIM];
    __shared__ float red[256];
    const int b = blockIdx.x, t = threadIdx.x;   // 256 threads

    if (t < K_DIM) cb[t] = c_buf[b * K_DIM + t];
    __syncthreads();

    {   // layer 1: 16 -> 256, relu
        float acc = be1[t];
#pragma unroll
        for (int k = 0; k < K_DIM; k++)
            acc = fmaf(cb[k], We1[k * E_DIM + t], acc);
        hE[t] = fmaxf(acc, 0.f);
    }
    __syncthreads();

    {   // layer 2: 256 -> 64, split across 4 partial groups
        const int o = t & 63, part = t >> 6;
        float acc = 0.f;
        const int e0 = part * 64;
#pragma unroll 8
        for (int e = e0; e < e0 + 64; e++)
            acc = fmaf(hE[e], We2[e * (2 * Z_DIM) + o], acc);
        red[t] = acc;
        __syncthreads();
        if (part == 0) {
            float r = (red[o] + red[o + 64]) + (red[o + 128] + red[o + 192]) + be2[o];
            if (o < Z_DIM) out[b * Z_DIM + o] = r;                            // mu
            else           out[B_DIM * Z_DIM + b * Z_DIM + (o - Z_DIM)] = r;  // logvar
        }
    }
}

// ---------------------------------------------------------------------------
extern "C" void kernel_launch(void* const* d_in, const int* in_sizes, int n_in,
                              void* d_out, int out_size)
{
    const float* x    = (const float*)d_in[0];
    const int*   mask = (const int*)  d_in[1];
    const float* fe   = (const float*)d_in[2];
    const float* fb   = (const float*)d_in[3];
    const float* W1   = (const float*)d_in[4];
    const float* b1   = (const float*)d_in[5];
    const float* W2   = (const float*)d_in[6];
    const float* b2   = (const float*)d_in[7];
    const float* We1  = (const float*)d_in[8];
    const float* be1  = (const float*)d_in[9];
    const float* We2  = (const float*)d_in[10];
    const float* be2  = (const float*)d_in[11];
    float* out = (float*)d_out;

    k_g     <<<D_DIM, H_DIM>>>(fe, fb, W1, b1);
    k_main  <<<NBLK, 128>>>(x, mask, W1, W2, b2);
    k_reduce<<<32, 256>>>();
    k_enc   <<<B_DIM, 256>>>(We1, be1, We2, be2, out);
}

// round 8
// speedup vs baseline: 3.0246x; 1.7397x over previous
#include <cuda_runtime.h>
#include <cstdint>

#define D_DIM 25000
#define B_DIM 64
#define K_DIM 16
#define H_DIM 128
#define E_DIM 256
#define Z_DIM 32

#define NBLK   592              // 148 SMs x 4 CTAs -> one wave
#define CHUNKS 3125             // 8 d's per chunk

// ---- scratch (device globals; no allocations allowed) ----
__device__ float g_buf[D_DIM * H_DIM];          // 12.8 MB: g[d][j]
__device__ float c_part[NBLK * B_DIM * K_DIM];  // per-block partial pooled c
__device__ float c_buf[B_DIM * K_DIM];          // pooled c [64][16]

// pack two fp32 -> bf16x2 {lo=a, hi=b}
__device__ __forceinline__ unsigned pkbf16(float a, float b) {
    unsigned r;
    asm("cvt.rn.bf16x2.f32 %0, %1, %2;" : "=r"(r) : "f"(b), "f"(a));
    return r;
}
__device__ __forceinline__ float bflo(unsigned p) { return __uint_as_float(p << 16); }
__device__ __forceinline__ float bfhi(unsigned p) { return __uint_as_float(p & 0xffff0000u); }

#define MMA(C, a0, a1, a2, a3, b0, b1)                                     \
    asm("mma.sync.aligned.m16n8k16.row.col.f32.bf16.bf16.f32 "             \
        "{%0,%1,%2,%3}, {%4,%5,%6,%7}, {%8,%9}, {%0,%1,%2,%3};"            \
        : "+f"((C)[0]), "+f"((C)[1]), "+f"((C)[2]), "+f"((C)[3])           \
        : "r"(a0), "r"(a1), "r"(a2), "r"(a3), "r"(b0), "r"(b1))

// ---------------------------------------------------------------------------
// Kernel 1: g[d][j] = b1[j] + feat_bias[d]*W1[17][j] + sum_i feat_emb[d][i]*W1[1+i][j]
// ---------------------------------------------------------------------------
__global__ void k_g(const float* __restrict__ fe, const float* __restrict__ fb,
                    const float* __restrict__ W1, const float* __restrict__ b1)
{
    int d = blockIdx.x;
    int j = threadIdx.x;                     // 128 threads
    float acc = b1[j] + fb[d] * W1[17 * H_DIM + j];
    const float* fr = fe + d * K_DIM;
#pragma unroll
    for (int i = 0; i < K_DIM; i++)
        acc = fmaf(fr[i], W1[(1 + i) * H_DIM + j], acc);
    g_buf[d * H_DIM + j] = acc;
}

// ---------------------------------------------------------------------------
// Kernel 2: main, tensor-core stage-2.
// Block = 128 thr = 4 warps. Warp w owns batches [16w,16w+16); all warps share d.
// Per d: A[16 rows=b, 128 cols=j] built IN fragment layout from h=relu(x*w0+g),
// split bf16 hi/lo; B = W2 (hi frags in regs, lo frags in smem table);
// 3 MMAs (hi*hi, hi*lo, lo*hi) per k-step per n-half, fp32 C.
// ---------------------------------------------------------------------------
__global__ __launch_bounds__(128, 4)
void k_main(const float* __restrict__ x, const int* __restrict__ mask,
            const float* __restrict__ W1, const float* __restrict__ W2,
            const float* __restrict__ b2)
{
    __shared__ __align__(16) float gs[8 * H_DIM];   // 4 KB g rows for chunk
    __shared__ __align__(16) float xs[8][B_DIM];    // 2 KB
    __shared__ __align__(16) float ms[8][B_DIM];    // 2 KB
    __shared__ __align__(16) float w0s[H_DIM];
    __shared__ __align__(16) uint2 wloS[16 * 32];   // W2-lo frags [ks*2+nh][lane], 4 KB

    const int t    = threadIdx.x;
    const int lane = t & 31;
    const int wrp  = t >> 5;
    const int g_l  = lane >> 2;     // 0..7  (row group)
    const int tt   = lane & 3;      // 0..3  (thread-in-group)
    const int bg   = wrp * 16;      // batch base of this warp

    if (t < H_DIM) w0s[t] = W1[t];

    // ---- W2 fragments: hi in regs (all warps), lo into smem table (warp 0) ----
    unsigned whi[8][2][2];
#pragma unroll
    for (int ks = 0; ks < 8; ks++) {
#pragma unroll
        for (int nh = 0; nh < 2; nh++) {
            const int j0 = ks * 16 + 2 * tt;
            const int n  = nh * 8 + g_l;
            float w00 = W2[(j0    ) * K_DIM + n];
            float w01 = W2[(j0 + 1) * K_DIM + n];
            float w10 = W2[(j0 + 8) * K_DIM + n];
            float w11 = W2[(j0 + 9) * K_DIM + n];
            unsigned h0 = pkbf16(w00, w01);
            unsigned h1 = pkbf16(w10, w11);
            whi[ks][nh][0] = h0;
            whi[ks][nh][1] = h1;
            if (wrp == 0) {
                unsigned l0 = pkbf16(w00 - bflo(h0), w01 - bfhi(h0));
                unsigned l1 = pkbf16(w10 - bflo(h1), w11 - bfhi(h1));
                wloS[(ks * 2 + nh) * 32 + lane] = make_uint2(l0, l1);
            }
        }
    }
    const float b2r0 = b2[2 * tt],     b2r1 = b2[2 * tt + 1];
    const float b2r2 = b2[8 + 2 * tt], b2r3 = b2[8 + 2 * tt + 1];

    float acc[8];
#pragma unroll
    for (int i = 0; i < 8; i++) acc[i] = 0.f;

    __syncthreads();

    // contiguous balanced chunk partition: 3125 = 165*6 + 427*5
    int cnt, base;
    if (blockIdx.x < 165) { cnt = 6; base = blockIdx.x * 6; }
    else                  { cnt = 5; base = 990 + (blockIdx.x - 165) * 5; }

    for (int ci = 0; ci < cnt; ci++) {
        const int d0 = (base + ci) * 8;

        // cooperative staging for 8 d's
        {
            const float4* src = (const float4*)(g_buf + d0 * H_DIM); // 256 float4
            ((float4*)gs)[t]       = src[t];
            ((float4*)gs)[t + 128] = src[t + 128];
            for (int i = t; i < 512; i += 128) {
                int b = i >> 3, qq = i & 7;
                int gi = b * D_DIM + d0 + qq;
                xs[qq][b] = x[gi];
                ms[qq][b] = (float)mask[gi];
            }
        }
        __syncthreads();

        for (int dq = 0; dq < 8; dq++) {
            const float* gsd = gs + dq * H_DIM;
            const float x0 = xs[dq][bg + g_l];
            const float x1 = xs[dq][bg + g_l + 8];
            const float m0 = ms[dq][bg + g_l];
            const float m1 = ms[dq][bg + g_l + 8];

            float Ca[2][4], Cb[2][4];
#pragma unroll
            for (int nh = 0; nh < 2; nh++)
#pragma unroll
                for (int i = 0; i < 4; i++) { Ca[nh][i] = 0.f; Cb[nh][i] = 0.f; }

#pragma unroll
            for (int ks = 0; ks < 8; ks++) {
                const int j0 = ks * 16 + 2 * tt;
                const float2 gA = *(const float2*)(gsd + j0);
                const float2 gB = *(const float2*)(gsd + j0 + 8);
                const float2 wA = *(const float2*)(w0s + j0);
                const float2 wB = *(const float2*)(w0s + j0 + 8);

                const float h00 = fmaxf(fmaf(x0, wA.x, gA.x), 0.f);
                const float h01 = fmaxf(fmaf(x0, wA.y, gA.y), 0.f);
                const float h02 = fmaxf(fmaf(x0, wB.x, gB.x), 0.f);
                const float h03 = fmaxf(fmaf(x0, wB.y, gB.y), 0.f);
                const float h10 = fmaxf(fmaf(x1, wA.x, gA.x), 0.f);
                const float h11 = fmaxf(fmaf(x1, wA.y, gA.y), 0.f);
                const float h12 = fmaxf(fmaf(x1, wB.x, gB.x), 0.f);
                const float h13 = fmaxf(fmaf(x1, wB.y, gB.y), 0.f);

                // A frags: a0(r=g,k=2t,2t+1) a1(r=g+8,same) a2(r=g,k=2t+8,+9) a3(r=g+8,same)
                const unsigned a0 = pkbf16(h00, h01);
                const unsigned a1 = pkbf16(h10, h11);
                const unsigned a2 = pkbf16(h02, h03);
                const unsigned a3 = pkbf16(h12, h13);
                const unsigned l0 = pkbf16(h00 - bflo(a0), h01 - bfhi(a0));
                const unsigned l1 = pkbf16(h10 - bflo(a1), h11 - bfhi(a1));
                const unsigned l2 = pkbf16(h02 - bflo(a2), h03 - bfhi(a2));
                const unsigned l3 = pkbf16(h12 - bflo(a3), h13 - bfhi(a3));

#pragma unroll
                for (int nh = 0; nh < 2; nh++) {
                    const uint2 wlo = wloS[(ks * 2 + nh) * 32 + lane];
                    MMA(Ca[nh], a0, a1, a2, a3, whi[ks][nh][0], whi[ks][nh][1]);
                    MMA(Cb[nh], a0, a1, a2, a3, wlo.x, wlo.y);
                    MMA(Cb[nh], l0, l1, l2, l3, whi[ks][nh][0], whi[ks][nh][1]);
                }
            }

            // epilogue: relu(s + b2) * mask, pooled into per-(b,k) accumulators
            // C layout: C[0]=(r=g,n=2t) C[1]=(r=g,n=2t+1) C[2]=(r=g+8,n=2t) C[3]=(r=g+8,n=2t+1)
            acc[0] = fmaf(m0, fmaxf(Ca[0][0] + Cb[0][0] + b2r0, 0.f), acc[0]);
            acc[1] = fmaf(m0, fmaxf(Ca[0][1] + Cb[0][1] + b2r1, 0.f), acc[1]);
            acc[2] = fmaf(m1, fmaxf(Ca[0][2] + Cb[0][2] + b2r0, 0.f), acc[2]);
            acc[3] = fmaf(m1, fmaxf(Ca[0][3] + Cb[0][3] + b2r1, 0.f), acc[3]);
            acc[4] = fmaf(m0, fmaxf(Ca[1][0] + Cb[1][0] + b2r2, 0.f), acc[4]);
            acc[5] = fmaf(m0, fmaxf(Ca[1][1] + Cb[1][1] + b2r3, 0.f), acc[5]);
            acc[6] = fmaf(m1, fmaxf(Ca[1][2] + Cb[1][2] + b2r2, 0.f), acc[6]);
            acc[7] = fmaf(m1, fmaxf(Ca[1][3] + Cb[1][3] + b2r3, 0.f), acc[7]);
        }
        __syncthreads();   // protect gs/xs/ms before next staging
    }

    // per-block partial store; warps own disjoint batches -> no reduction needed
    float* cp = c_part + blockIdx.x * (B_DIM * K_DIM);
    const int b0r = bg + g_l, b1r = bg + g_l + 8;
    cp[b0r * K_DIM +     2 * tt    ] = acc[0];
    cp[b0r * K_DIM +     2 * tt + 1] = acc[1];
    cp[b1r * K_DIM +     2 * tt    ] = acc[2];
    cp[b1r * K_DIM +     2 * tt + 1] = acc[3];
    cp[b0r * K_DIM + 8 + 2 * tt    ] = acc[4];
    cp[b0r * K_DIM + 8 + 2 * tt + 1] = acc[5];
    cp[b1r * K_DIM + 8 + 2 * tt    ] = acc[6];
    cp[b1r * K_DIM + 8 + 2 * tt + 1] = acc[7];
}

// ---------------------------------------------------------------------------
// Kernel 3: reduce 592 partials -> c_buf.  grid 32 x 256; 8 lanes per output.
// ---------------------------------------------------------------------------
__global__ void k_reduce()
{
    const int t = threadIdx.x;
    const int o = blockIdx.x * 32 + (t >> 3);   // 0..1023
    const int s = t & 7;
    float a0 = 0.f, a1 = 0.f;
    for (int bk = s; bk < NBLK; bk += 16) {     // 592 = 16*37
        a0 += c_part[bk * 1024 + o];
        a1 += c_part[(bk + 8) * 1024 + o];
    }
    float v = a0 + a1;
    v += __shfl_xor_sync(0xffffffff, v, 4);
    v += __shfl_xor_sync(0xffffffff, v, 2);
    v += __shfl_xor_sync(0xffffffff, v, 1);
    if (s == 0) c_buf[o] = v;
}

// ---------------------------------------------------------------------------
// Kernel 4: fused encoder MLP + split (mu||logvar) output layout.
// ---------------------------------------------------------------------------
__global__ void k_enc(const float* __restrict__ We1, const float* __restrict__ be1,
                      const float* __restrict__ We2, const float* __restrict__ be2,
                      float* __restrict__ out)
{
    __shared__ float cb[K_DIM];
    __shared__ float hE[E_DIM];
    __shared__ float red[256];
    const int b = blockIdx.x, t = threadIdx.x;   // 256 threads

    if (t < K_DIM) cb[t] = c_buf[b * K_DIM + t];
    __syncthreads();

    {   // layer 1: 16 -> 256, relu
        float acc = be1[t];
#pragma unroll
        for (int k = 0; k < K_DIM; k++)
            acc = fmaf(cb[k], We1[k * E_DIM + t], acc);
        hE[t] = fmaxf(acc, 0.f);
    }
    __syncthreads();

    {   // layer 2: 256 -> 64, split across 4 partial groups
        const int o = t & 63, part = t >> 6;
        float acc = 0.f;
        const int e0 = part * 64;
#pragma unroll 8
        for (int e = e0; e < e0 + 64; e++)
            acc = fmaf(hE[e], We2[e * (2 * Z_DIM) + o], acc);
        red[t] = acc;
        __syncthreads();
        if (part == 0) {
            float r = (red[o] + red[o + 64]) + (red[o + 128] + red[o + 192]) + be2[o];
            if (o < Z_DIM) out[b * Z_DIM + o] = r;                            // mu
            else           out[B_DIM * Z_DIM + b * Z_DIM + (o - Z_DIM)] = r;  // logvar
        }
    }
}

// ---------------------------------------------------------------------------
extern "C" void kernel_launch(void* const* d_in, const int* in_sizes, int n_in,
                              void* d_out, int out_size)
{
    const float* x    = (const float*)d_in[0];
    const int*   mask = (const int*)  d_in[1];
    const float* fe   = (const float*)d_in[2];
    const float* fb   = (const float*)d_in[3];
    const float* W1   = (const float*)d_in[4];
    const float* b1   = (const float*)d_in[5];
    const float* W2   = (const float*)d_in[6];
    const float* b2   = (const float*)d_in[7];
    const float* We1  = (const float*)d_in[8];
    const float* be1  = (const float*)d_in[9];
    const float* We2  = (const float*)d_in[10];
    const float* be2  = (const float*)d_in[11];
    float* out = (float*)d_out;

    k_g     <<<D_DIM, H_DIM>>>(fe, fb, W1, b1);
    k_main  <<<NBLK, 128>>>(x, mask, W1, W2, b2);
    k_reduce<<<32, 256>>>();
    k_enc   <<<B_DIM, 256>>>(We1, be1, We2, be2, out);
}

// round 9
// speedup vs baseline: 4.1619x; 1.3760x over previous
#include <cuda_runtime.h>
#include <cstdint>

#define D_DIM 25000
#define B_DIM 64
#define K_DIM 16
#define H_DIM 128
#define E_DIM 256
#define Z_DIM 32

#define NBLK   592              // 148 SMs x 4 CTAs -> one wave
#define CHUNKS 3125             // 8 d's per chunk

// ---- scratch (device globals; no allocations allowed) ----
__device__ float g_buf[D_DIM * H_DIM];          // 12.8 MB: g[d][j]
__device__ float c_part[NBLK * B_DIM * K_DIM];  // per-block partial pooled c

// pack two fp32 -> bf16x2 {lo=a, hi=b}
__device__ __forceinline__ unsigned pkbf16(float a, float b) {
    unsigned r;
    asm("cvt.rn.bf16x2.f32 %0, %1, %2;" : "=r"(r) : "f"(b), "f"(a));
    return r;
}
__device__ __forceinline__ float bflo(unsigned p) { return __uint_as_float(p << 16); }
__device__ __forceinline__ float bfhi(unsigned p) { return __uint_as_float(p & 0xffff0000u); }
// packed bf16x2 relu
__device__ __forceinline__ unsigned relu2(unsigned a) {
    unsigned r;
    asm("max.bf16x2 %0, %1, %2;" : "=r"(r) : "r"(a), "r"(0u));
    return r;
}

#define MMA(C, a0, a1, a2, a3, b0, b1)                                     \
    asm("mma.sync.aligned.m16n8k16.row.col.f32.bf16.bf16.f32 "             \
        "{%0,%1,%2,%3}, {%4,%5,%6,%7}, {%8,%9}, {%0,%1,%2,%3};"            \
        : "+f"((C)[0]), "+f"((C)[1]), "+f"((C)[2]), "+f"((C)[3])           \
        : "r"(a0), "r"(a1), "r"(a2), "r"(a3), "r"(b0), "r"(b1))

// ---------------------------------------------------------------------------
// Kernel 1: g[d][j] = b1[j] + feat_bias[d]*W1[17][j] + sum_i feat_emb[d][i]*W1[1+i][j]
// 2 d's per block (256 threads).
// ---------------------------------------------------------------------------
__global__ void k_g(const float* __restrict__ fe, const float* __restrict__ fb,
                    const float* __restrict__ W1, const float* __restrict__ b1)
{
    const int d = blockIdx.x * 2 + (threadIdx.x >> 7);
    const int j = threadIdx.x & 127;
    float acc = b1[j] + fb[d] * W1[17 * H_DIM + j];
    const float* fr = fe + d * K_DIM;
#pragma unroll
    for (int i = 0; i < K_DIM; i++)
        acc = fmaf(fr[i], W1[(1 + i) * H_DIM + j], acc);
    g_buf[d * H_DIM + j] = acc;
}

// ---------------------------------------------------------------------------
// Kernel 2: main, tensor-core stage-2.
// Block = 128 thr = 4 warps. Warp w owns batches [16w,16w+16); all warps share d.
// A[16 b x 128 j] built in-fragment: h = relu(x*w0 + g) (relu in bf16x2).
// 4 MMAs per ks: Ca += a*W2hi (2 n-halves), Cb += a*W2lo (compensation).
// ---------------------------------------------------------------------------
__global__ __launch_bounds__(128, 4)
void k_main(const float* __restrict__ x, const int* __restrict__ mask,
            const float* __restrict__ W1, const float* __restrict__ W2,
            const float* __restrict__ b2)
{
    __shared__ __align__(16) float gs[8 * H_DIM];   // 4 KB g rows for chunk
    __shared__ __align__(16) float xs[8][B_DIM];    // 2 KB
    __shared__ __align__(16) float ms[8][B_DIM];    // 2 KB
    __shared__ __align__(16) float w0s[H_DIM];
    __shared__ __align__(16) uint2 wloS[16 * 32];   // W2-lo frags [ks*2+nh][lane], 4 KB

    const int t    = threadIdx.x;
    const int lane = t & 31;
    const int wrp  = t >> 5;
    const int g_l  = lane >> 2;     // 0..7  (row group)
    const int tt   = lane & 3;      // 0..3  (thread-in-group)
    const int bg   = wrp * 16;      // batch base of this warp

    if (t < H_DIM) w0s[t] = W1[t];

    // ---- W2 fragments: hi in regs (all warps), lo into smem table (warp 0) ----
    unsigned whi[8][2][2];
#pragma unroll
    for (int ks = 0; ks < 8; ks++) {
#pragma unroll
        for (int nh = 0; nh < 2; nh++) {
            const int j0 = ks * 16 + 2 * tt;
            const int n  = nh * 8 + g_l;
            float w00 = W2[(j0    ) * K_DIM + n];
            float w01 = W2[(j0 + 1) * K_DIM + n];
            float w10 = W2[(j0 + 8) * K_DIM + n];
            float w11 = W2[(j0 + 9) * K_DIM + n];
            unsigned h0 = pkbf16(w00, w01);
            unsigned h1 = pkbf16(w10, w11);
            whi[ks][nh][0] = h0;
            whi[ks][nh][1] = h1;
            if (wrp == 0) {
                unsigned l0 = pkbf16(w00 - bflo(h0), w01 - bfhi(h0));
                unsigned l1 = pkbf16(w10 - bflo(h1), w11 - bfhi(h1));
                wloS[(ks * 2 + nh) * 32 + lane] = make_uint2(l0, l1);
            }
        }
    }
    const float b2r0 = b2[2 * tt],     b2r1 = b2[2 * tt + 1];
    const float b2r2 = b2[8 + 2 * tt], b2r3 = b2[8 + 2 * tt + 1];

    float acc[8];
#pragma unroll
    for (int i = 0; i < 8; i++) acc[i] = 0.f;

    __syncthreads();

    // contiguous balanced chunk partition: 3125 = 165*6 + 427*5
    int cnt, base;
    if (blockIdx.x < 165) { cnt = 6; base = blockIdx.x * 6; }
    else                  { cnt = 5; base = 990 + (blockIdx.x - 165) * 5; }

    for (int ci = 0; ci < cnt; ci++) {
        const int d0 = (base + ci) * 8;

        // cooperative staging for 8 d's
        {
            const float4* src = (const float4*)(g_buf + d0 * H_DIM); // 256 float4
            ((float4*)gs)[t]       = src[t];
            ((float4*)gs)[t + 128] = src[t + 128];
            for (int i = t; i < 512; i += 128) {
                int b = i >> 3, qq = i & 7;
                int gi = b * D_DIM + d0 + qq;
                xs[qq][b] = x[gi];
                ms[qq][b] = (float)mask[gi];
            }
        }
        __syncthreads();

        for (int dq = 0; dq < 8; dq++) {
            const float* gsd = gs + dq * H_DIM;
            const float x0 = xs[dq][bg + g_l];
            const float x1 = xs[dq][bg + g_l + 8];
            const float m0 = ms[dq][bg + g_l];
            const float m1 = ms[dq][bg + g_l + 8];

            float Ca[2][4], Cb[2][4];
#pragma unroll
            for (int nh = 0; nh < 2; nh++)
#pragma unroll
                for (int i = 0; i < 4; i++) { Ca[nh][i] = 0.f; Cb[nh][i] = 0.f; }

#pragma unroll
            for (int ks = 0; ks < 8; ks++) {
                const int j0 = ks * 16 + 2 * tt;
                const float2 gA = *(const float2*)(gsd + j0);
                const float2 gB = *(const float2*)(gsd + j0 + 8);
                const float2 wA = *(const float2*)(w0s + j0);
                const float2 wB = *(const float2*)(w0s + j0 + 8);

                const float h00 = fmaf(x0, wA.x, gA.x);
                const float h01 = fmaf(x0, wA.y, gA.y);
                const float h02 = fmaf(x0, wB.x, gB.x);
                const float h03 = fmaf(x0, wB.y, gB.y);
                const float h10 = fmaf(x1, wA.x, gA.x);
                const float h11 = fmaf(x1, wA.y, gA.y);
                const float h12 = fmaf(x1, wB.x, gB.x);
                const float h13 = fmaf(x1, wB.y, gB.y);

                // A frags with relu applied packed (bf16x2 max vs 0)
                const unsigned a0 = relu2(pkbf16(h00, h01));
                const unsigned a1 = relu2(pkbf16(h10, h11));
                const unsigned a2 = relu2(pkbf16(h02, h03));
                const unsigned a3 = relu2(pkbf16(h12, h13));

#pragma unroll
                for (int nh = 0; nh < 2; nh++) {
                    const uint2 wlo = wloS[(ks * 2 + nh) * 32 + lane];
                    MMA(Ca[nh], a0, a1, a2, a3, whi[ks][nh][0], whi[ks][nh][1]);
                    MMA(Cb[nh], a0, a1, a2, a3, wlo.x, wlo.y);
                }
            }

            // epilogue: relu(s + b2) * mask, pooled
            acc[0] = fmaf(m0, fmaxf(Ca[0][0] + Cb[0][0] + b2r0, 0.f), acc[0]);
            acc[1] = fmaf(m0, fmaxf(Ca[0][1] + Cb[0][1] + b2r1, 0.f), acc[1]);
            acc[2] = fmaf(m1, fmaxf(Ca[0][2] + Cb[0][2] + b2r0, 0.f), acc[2]);
            acc[3] = fmaf(m1, fmaxf(Ca[0][3] + Cb[0][3] + b2r1, 0.f), acc[3]);
            acc[4] = fmaf(m0, fmaxf(Ca[1][0] + Cb[1][0] + b2r2, 0.f), acc[4]);
            acc[5] = fmaf(m0, fmaxf(Ca[1][1] + Cb[1][1] + b2r3, 0.f), acc[5]);
            acc[6] = fmaf(m1, fmaxf(Ca[1][2] + Cb[1][2] + b2r2, 0.f), acc[6]);
            acc[7] = fmaf(m1, fmaxf(Ca[1][3] + Cb[1][3] + b2r3, 0.f), acc[7]);
        }
        __syncthreads();   // protect gs/xs/ms before next staging
    }

    // per-block partial store; warps own disjoint batches -> no reduction needed
    float* cp = c_part + blockIdx.x * (B_DIM * K_DIM);
    const int b0r = bg + g_l, b1r = bg + g_l + 8;
    cp[b0r * K_DIM +     2 * tt    ] = acc[0];
    cp[b0r * K_DIM +     2 * tt + 1] = acc[1];
    cp[b1r * K_DIM +     2 * tt    ] = acc[2];
    cp[b1r * K_DIM +     2 * tt + 1] = acc[3];
    cp[b0r * K_DIM + 8 + 2 * tt    ] = acc[4];
    cp[b0r * K_DIM + 8 + 2 * tt + 1] = acc[5];
    cp[b1r * K_DIM + 8 + 2 * tt    ] = acc[6];
    cp[b1r * K_DIM + 8 + 2 * tt + 1] = acc[7];
}

// ---------------------------------------------------------------------------
// Kernel 3: fused partial-reduce + encoder MLP + split (mu||logvar) output.
// Block b reduces its own 592 partials (16 k-values), then runs the MLP.
// ---------------------------------------------------------------------------
__global__ void k_enc(const float* __restrict__ We1, const float* __restrict__ be1,
                      const float* __restrict__ We2, const float* __restrict__ be2,
                      float* __restrict__ out)
{
    __shared__ float red16[16][17];
    __shared__ float cb[K_DIM];
    __shared__ float hE[E_DIM];
    __shared__ float red[256];
    const int b = blockIdx.x, t = threadIdx.x;   // 256 threads

    {   // deterministic reduce of c_part[:, b, :]: 16 slices per k
        const int k = t & 15, s = t >> 4;
        float a = 0.f;
        for (int bk = s; bk < NBLK; bk += 16)    // 37 iters
            a += c_part[bk * (B_DIM * K_DIM) + b * K_DIM + k];
        red16[s][k] = a;
    }
    __syncthreads();
    if (t < K_DIM) {
        float v = 0.f;
#pragma unroll
        for (int s = 0; s < 16; s++) v += red16[s][t];
        cb[t] = v;
    }
    __syncthreads();

    {   // layer 1: 16 -> 256, relu
        float acc = be1[t];
#pragma unroll
        for (int k = 0; k < K_DIM; k++)
            acc = fmaf(cb[k], We1[k * E_DIM + t], acc);
        hE[t] = fmaxf(acc, 0.f);
    }
    __syncthreads();

    {   // layer 2: 256 -> 64, split across 4 partial groups
        const int o = t & 63, part = t >> 6;
        float acc = 0.f;
        const int e0 = part * 64;
#pragma unroll 8
        for (int e = e0; e < e0 + 64; e++)
            acc = fmaf(hE[e], We2[e * (2 * Z_DIM) + o], acc);
        red[t] = acc;
        __syncthreads();
        if (part == 0) {
            float r = (red[o] + red[o + 64]) + (red[o + 128] + red[o + 192]) + be2[o];
            if (o < Z_DIM) out[b * Z_DIM + o] = r;                            // mu
            else           out[B_DIM * Z_DIM + b * Z_DIM + (o - Z_DIM)] = r;  // logvar
        }
    }
}

// ---------------------------------------------------------------------------
extern "C" void kernel_launch(void* const* d_in, const int* in_sizes, int n_in,
                              void* d_out, int out_size)
{
    const float* x    = (const float*)d_in[0];
    const int*   mask = (const int*)  d_in[1];
    const float* fe   = (const float*)d_in[2];
    const float* fb   = (const float*)d_in[3];
    const float* W1   = (const float*)d_in[4];
    const float* b1   = (const float*)d_in[5];
    const float* W2   = (const float*)d_in[6];
    const float* b2   = (const float*)d_in[7];
    const float* We1  = (const float*)d_in[8];
    const float* be1  = (const float*)d_in[9];
    const float* We2  = (const float*)d_in[10];
    const float* be2  = (const float*)d_in[11];
    float* out = (float*)d_out;

    k_g   <<<D_DIM / 2, 256>>>(fe, fb, W1, b1);
    k_main<<<NBLK, 128>>>(x, mask, W1, W2, b2);
    k_enc <<<B_DIM, 256>>>(We1, be1, We2, be2, out);
}